// round 13
// baseline (speedup 1.0000x reference)
#include <cuda_runtime.h>
#include <cuda_bf16.h>

// B=524288, D=256, C=1000 (D hardcoded for thread-per-element layout).
#define D_DIM 256
#define C_MAX 1024
#define NBLK 128          // bin blocks (fixed cell grid)
#define CELL_CAP 24       // entries per (class, bin-block) cell; Poisson mean 4.1
#define SLOTS (NBLK * CELL_CAP)   // 3072 slots per class
#define ALL_CAP 1024      // compacted per-class list capacity (max count ~650)
#define BIN_CHUNK 4096    // labels per bin block

// Scratch: __device__ globals. g_cellcnt/g_bucket are fully overwritten by
// bin each run (no cleanup needed); scalars self-clean via last-block reset.
__device__ int           g_bucket[C_MAX * SLOTS];     // 12.6 MB, slot-addressed
__device__ unsigned char g_cellcnt[C_MAX * NBLK];     // 128 KB
__device__ float g_loss_sum;
__device__ int   g_n_present;
__device__ int   g_done;

// ---------------------------------------------------------------------------
// Kernel 1: binning with DETERMINISTIC slots. Block b owns rows
// [b*4096,(b+1)*4096) (ascending) and writes class c's entries into the fixed
// cell bucket[c][b][*]. No global reservation atomics; concatenating cells in
// block order yields a globally SORTED row list per class.
// ---------------------------------------------------------------------------
__global__ void __launch_bounds__(1024) bin_kernel(const void* __restrict__ lraw,
                                                   int B, int C) {
    __shared__ unsigned short s_lab[BIN_CHUNK];   // 8 KB
    __shared__ int s_hist[C_MAX];                 // 4 KB (hist, then cursor)
    __shared__ int s_bad;

    const int tid = threadIdx.x;
    const int b   = blockIdx.x;
    if (tid == 0) s_bad = 0;
    for (int i = tid; i < C_MAX; i += 1024) s_hist[i] = 0;
    __syncthreads();

    const long long* __restrict__ l64 = (const long long*)lraw;
    const int* __restrict__       l32 = (const int*)lraw;

    {   // dtype detect: int64 vs int32 storage (range-check first 1024 as i64)
        const int n = (B < 1024) ? B : 1024;
        int bad = 0;
        for (int i = tid; i < n; i += 1024) {
            const long long v = l64[i];
            if (v < 0 || v >= (long long)C) bad = 1;
        }
        if (bad) atomicOr(&s_bad, 1);
    }
    __syncthreads();
    const bool is64 = (s_bad == 0);

    const int start = b * BIN_CHUNK;
    const int end   = (start + BIN_CHUNK < B) ? (start + BIN_CHUNK) : B;
    const int cnt   = (end > start) ? (end - start) : 0;

    // Phase A: decode + local histogram
    for (int i = tid; i < cnt; i += 1024) {
        const int c = is64 ? (int)l64[start + i] : l32[start + i];
        s_lab[i] = (unsigned short)c;
        atomicAdd(&s_hist[c], 1);
    }
    __syncthreads();

    // Phase B: publish per-cell counts (plain stores), reset hist as cursor
    for (int c = tid; c < C; c += 1024) {
        const int h = s_hist[c];
        g_cellcnt[c * NBLK + b] = (unsigned char)((h < CELL_CAP) ? h : CELL_CAP);
        s_hist[c] = 0;
    }
    __syncthreads();

    // Phase C: scatter row indices into this block's fixed cells
    for (int i = tid; i < cnt; i += 1024) {
        const int c   = s_lab[i];
        const int pos = atomicAdd(&s_hist[c], 1);
        if (pos < CELL_CAP)
            g_bucket[c * SLOTS + b * CELL_CAP + pos] = start + i;
    }
}

// ---------------------------------------------------------------------------
// Block reduce over 256 threads (8 warps)
// ---------------------------------------------------------------------------
__device__ __forceinline__ float block_reduce_256(float v, float* s_red, int tid) {
    #pragma unroll
    for (int o = 16; o > 0; o >>= 1) v += __shfl_down_sync(0xffffffffu, v, o);
    if ((tid & 31) == 0) s_red[tid >> 5] = v;
    __syncthreads();
    if (tid < 32) {
        v = (tid < 8) ? s_red[tid] : 0.0f;
        #pragma unroll
        for (int o = 4; o > 0; o >>= 1) v += __shfl_down_sync(0xffffffffu, v, o);
        if (tid == 0) s_red[0] = v;
    }
    __syncthreads();
    const float r = s_red[0];
    __syncthreads();
    return r;
}

// ---------------------------------------------------------------------------
// Kernel 2: one block per class. Scan cell counts -> compact slots into smem
// (SORTED row list by construction) -> gather in ascending row order. Since
// every class's j-th entry ~= j/count*B, the 1000 concurrent blocks sweep x
// front-to-back together (narrow moving DRAM window instead of uniform
// random). Per-class math identical to the proven kernel.
// ---------------------------------------------------------------------------
__global__ void __launch_bounds__(256) class_kernel(
    const float* __restrict__ x,
    const float* __restrict__ cimg,
    const float* __restrict__ cskt,
    float* __restrict__ out)
{
    const int c   = blockIdx.x;
    const int tid = threadIdx.x;
    const int q   = tid >> 6;        // row slot 0..3
    const int ds  = tid & 63;        // float4 index within a 256-float row

    __shared__ __align__(16) float s_part[4 * 256];   // 4 KB
    __shared__ __align__(16) int   s_all[ALL_CAP];    // 4 KB sorted row list
    __shared__ int   s_cnt[NBLK];
    __shared__ int   s_scan[NBLK];
    __shared__ float s_red[32];

    // Load per-cell counts + inclusive scan (Hillis-Steele over 128)
    if (tid < NBLK) {
        const int v = (int)g_cellcnt[c * NBLK + tid];
        s_cnt[tid]  = v;
        s_scan[tid] = v;
    }
    __syncthreads();
    #pragma unroll
    for (int d = 1; d < NBLK; d <<= 1) {
        int v = 0;
        if (tid < NBLK) {
            v = s_scan[tid];
            if (tid >= d) v += s_scan[tid - d];
        }
        __syncthreads();
        if (tid < NBLK) s_scan[tid] = v;
        __syncthreads();
    }
    const int count = s_scan[NBLK - 1];

    if (count > 0) {
        // Compact: coalesced read of all 3072 slots, predicated write to
        // s_all at the scanned offset. Result: globally ascending rows.
        for (int s = tid; s < SLOTS; s += 256) {
            const int b = s / CELL_CAP;
            const int k = s - b * CELL_CAP;
            const int v = g_bucket[c * SLOTS + s];
            if (k < s_cnt[b]) {
                const int idx = s_scan[b] - s_cnt[b] + k;
                if (idx < ALL_CAP) s_all[idx] = v;
            }
        }
        __syncthreads();

        const int m = (count < ALL_CAP) ? count : ALL_CAP;
        float4 acc = make_float4(0.f, 0.f, 0.f, 0.f);

        int j = 0;
        for (; j + 16 <= m; j += 16) {
            const int r0 = s_all[j      + q];
            const int r1 = s_all[j + 4  + q];
            const int r2 = s_all[j + 8  + q];
            const int r3 = s_all[j + 12 + q];
            const float4 v0 = __ldg((const float4*)(x + (size_t)r0 * D_DIM) + ds);
            const float4 v1 = __ldg((const float4*)(x + (size_t)r1 * D_DIM) + ds);
            const float4 v2 = __ldg((const float4*)(x + (size_t)r2 * D_DIM) + ds);
            const float4 v3 = __ldg((const float4*)(x + (size_t)r3 * D_DIM) + ds);
            acc.x += v0.x + v1.x + v2.x + v3.x;
            acc.y += v0.y + v1.y + v2.y + v3.y;
            acc.z += v0.z + v1.z + v2.z + v3.z;
            acc.w += v0.w + v1.w + v2.w + v3.w;
        }
        for (; j < m; j += 4) {
            const int idx = j + q;
            if (idx < m) {
                const int r = s_all[idx];
                const float4 v = __ldg((const float4*)(x + (size_t)r * D_DIM) + ds);
                acc.x += v.x; acc.y += v.y; acc.z += v.z; acc.w += v.w;
            }
        }

        // Combine the 4 row-slot partial sums across q via smem.
        __syncthreads();
        *((float4*)(s_part + q * 256) + ds) = acc;
        __syncthreads();
        const float sum = s_part[0 * 256 + tid] + s_part[1 * 256 + tid] +
                          s_part[2 * 256 + tid] + s_part[3 * 256 + tid];

        const float mean = sum / (float)count;
        const float ci   = cimg[c * D_DIM + tid];
        const float upd  = fmaf(ci, 0.9f, mean * 0.1f);

        const float nrm2 = block_reduce_256(upd * upd, s_red, tid);
        const float v    = upd * rsqrtf(nrm2);

        const float d  = v - cskt[c * D_DIM + tid];
        const float sq = block_reduce_256(d * d, s_red, tid);

        if (tid == 0) {
            atomicAdd(&g_loss_sum, sq);
            atomicAdd(&g_n_present, 1);
        }
    }

    // Completion protocol: last block finalizes the scalar and resets scratch.
    if (tid == 0) {
        __threadfence();
        const int t = atomicAdd(&g_done, 1);
        if (t == (int)gridDim.x - 1) {
            const float ls = atomicAdd(&g_loss_sum, 0.0f);   // coherent read
            int np = atomicAdd(&g_n_present, 0);
            if (np < 1) np = 1;
            out[0] = ls / (float)np;
            g_loss_sum  = 0.0f;
            g_n_present = 0;
            g_done      = 0;
        }
    }
}

// ---------------------------------------------------------------------------
extern "C" void kernel_launch(void* const* d_in, const int* in_sizes, int n_in,
                              void* d_out, int out_size) {
    const float* x    = (const float*)d_in[0];
    const void*  lraw = d_in[1];
    const float* cimg = (const float*)d_in[2];
    const float* cskt = (const float*)d_in[3];
    float* out = (float*)d_out;

    const int B = in_sizes[1];           // 524288 (= NBLK * BIN_CHUNK exactly)
    const int C = in_sizes[2] / D_DIM;   // 1000

    bin_kernel<<<NBLK, 1024>>>(lraw, B, C);
    class_kernel<<<C, 256>>>(x, cimg, cskt, out);
}

// round 14
// speedup vs baseline: 1.0767x; 1.0767x over previous
#include <cuda_runtime.h>
#include <cuda_bf16.h>

// B=524288, D=256, C=1000 (D hardcoded for thread-per-element layout).
#define D_DIM 256
#define C_MAX 1024
#define BUCKET_CAP 2048     // expected ~524/class, Poisson max ~650
#define CNT_PAD 32          // one counter per 128B line -> distinct LTS slices
#define BIN_CHUNK 2048      // labels per bin block (256 blocks)

// Scratch: __device__ globals (zero-initialized at load; self-cleaned per run).
__device__ int   g_counts[C_MAX * CNT_PAD];   // padded counters (128 KB)
__device__ int   g_bucket[C_MAX * BUCKET_CAP];
__device__ float g_loss_sum;
__device__ int   g_n_present;
__device__ int   g_done;

// ---------------------------------------------------------------------------
// Kernel 1: two-level binning (proven design; 256 blocks x 2048 labels for
// max phase A/C parallelism — 128 > 64 blocks was measured, extrapolating up).
// ---------------------------------------------------------------------------
__global__ void __launch_bounds__(1024) bin_kernel(const void* __restrict__ lraw,
                                                   int B, int C) {
    __shared__ unsigned short s_lab[BIN_CHUNK];   // 4 KB
    __shared__ int s_hist[C_MAX];                 // 4 KB (hist, then cursor)
    __shared__ int s_base[C_MAX];                 // 4 KB
    __shared__ int s_bad;

    const int tid = threadIdx.x;
    if (tid == 0) s_bad = 0;
    for (int i = tid; i < C_MAX; i += 1024) s_hist[i] = 0;
    __syncthreads();

    const long long* __restrict__ l64 = (const long long*)lraw;
    const int* __restrict__       l32 = (const int*)lraw;

    {   // dtype detect: int64 vs int32 storage (range-check first 1024 as i64)
        const int n = (B < 1024) ? B : 1024;
        int bad = 0;
        for (int i = tid; i < n; i += 1024) {
            const long long v = l64[i];
            if (v < 0 || v >= (long long)C) bad = 1;
        }
        if (bad) atomicOr(&s_bad, 1);
    }
    __syncthreads();
    const bool is64 = (s_bad == 0);

    const int start = blockIdx.x * BIN_CHUNK;
    const int end   = (start + BIN_CHUNK < B) ? (start + BIN_CHUNK) : B;
    const int cnt   = (end > start) ? (end - start) : 0;

    // Phase A: decode + local histogram
    for (int i = tid; i < cnt; i += 1024) {
        const int c = is64 ? (int)l64[start + i] : l32[start + i];
        s_lab[i] = (unsigned short)c;
        atomicAdd(&s_hist[c], 1);
    }
    __syncthreads();

    // Phase B: reserve global ranges (staggered start per block);
    // reset hist for reuse as cursor.
    {
        const int off = (blockIdx.x * 19) % C;
        for (int k = tid; k < C; k += 1024) {
            int c = k + off;
            if (c >= C) c -= C;
            const int h = s_hist[c];
            s_base[c] = h ? atomicAdd(&g_counts[c * CNT_PAD], h) : 0;
            s_hist[c] = 0;
        }
    }
    __syncthreads();

    // Phase C: scatter row indices into reserved (contiguous) slots
    for (int i = tid; i < cnt; i += 1024) {
        const int c   = s_lab[i];
        const int pos = s_base[c] + atomicAdd(&s_hist[c], 1);
        if (pos < BUCKET_CAP) g_bucket[c * BUCKET_CAP + pos] = start + i;
    }
}

// ---------------------------------------------------------------------------
// Block reduce over 256 threads (8 warps)
// ---------------------------------------------------------------------------
__device__ __forceinline__ float block_reduce_256(float v, float* s_red, int tid) {
    #pragma unroll
    for (int o = 16; o > 0; o >>= 1) v += __shfl_down_sync(0xffffffffu, v, o);
    if ((tid & 31) == 0) s_red[tid >> 5] = v;
    __syncthreads();
    if (tid < 32) {
        v = (tid < 8) ? s_red[tid] : 0.0f;
        #pragma unroll
        for (int o = 4; o > 0; o >>= 1) v += __shfl_down_sync(0xffffffffu, v, o);
        if (tid == 0) s_red[0] = v;
    }
    __syncthreads();
    const float r = s_red[0];
    __syncthreads();
    return r;
}

// ---------------------------------------------------------------------------
// Kernel 2: R5/R10 class kernel VERBATIM — the measured optimum across 5
// independent experiments (87.5-91us @ 74-76% DRAM; insensitive to MLP,
// occupancy, scheduling, PDL, and request order — this is the gather ceiling).
// ---------------------------------------------------------------------------
__global__ void __launch_bounds__(256) class_kernel(
    const float* __restrict__ x,
    const float* __restrict__ cimg,
    const float* __restrict__ cskt,
    float* __restrict__ out)
{
    const int c   = blockIdx.x;
    const int tid = threadIdx.x;
    const int q   = tid >> 6;        // row slot 0..3
    const int ds  = tid & 63;        // float4 index within a 256-float row

    __shared__ __align__(16) float s_part[4 * 256];
    __shared__ __align__(16) int   s_rows[512];
    __shared__ float s_red[32];
    __shared__ int   s_count;

    if (tid == 0) {
        s_count = g_counts[c * CNT_PAD];
        g_counts[c * CNT_PAD] = 0;   // self-clean for next graph replay
    }
    __syncthreads();
    const int count = s_count;

    if (count > 0) {
        const int m = (count < BUCKET_CAP) ? count : BUCKET_CAP;
        const int* __restrict__ bucket = &g_bucket[c * BUCKET_CAP];

        float4 acc = make_float4(0.f, 0.f, 0.f, 0.f);

        for (int base = 0; base < m; base += 512) {
            const int seg = (m - base < 512) ? (m - base) : 512;
            __syncthreads();
            for (int t = tid; t < seg; t += 256) s_rows[t] = bucket[base + t];
            __syncthreads();

            int j = 0;
            for (; j + 16 <= seg; j += 16) {
                const int r0 = s_rows[j      + q];
                const int r1 = s_rows[j + 4  + q];
                const int r2 = s_rows[j + 8  + q];
                const int r3 = s_rows[j + 12 + q];
                const float4 v0 = __ldg((const float4*)(x + (size_t)r0 * D_DIM) + ds);
                const float4 v1 = __ldg((const float4*)(x + (size_t)r1 * D_DIM) + ds);
                const float4 v2 = __ldg((const float4*)(x + (size_t)r2 * D_DIM) + ds);
                const float4 v3 = __ldg((const float4*)(x + (size_t)r3 * D_DIM) + ds);
                acc.x += v0.x + v1.x + v2.x + v3.x;
                acc.y += v0.y + v1.y + v2.y + v3.y;
                acc.z += v0.z + v1.z + v2.z + v3.z;
                acc.w += v0.w + v1.w + v2.w + v3.w;
            }
            for (; j < seg; j += 4) {
                const int idx = j + q;
                if (idx < seg) {
                    const int r = s_rows[idx];
                    const float4 v = __ldg((const float4*)(x + (size_t)r * D_DIM) + ds);
                    acc.x += v.x; acc.y += v.y; acc.z += v.z; acc.w += v.w;
                }
            }
        }

        // Combine the 4 row-slot partial sums across q via smem.
        __syncthreads();
        *((float4*)(s_part + q * 256) + ds) = acc;
        __syncthreads();
        const float sum = s_part[0 * 256 + tid] + s_part[1 * 256 + tid] +
                          s_part[2 * 256 + tid] + s_part[3 * 256 + tid];

        const float mean = sum / (float)count;
        const float ci   = cimg[c * D_DIM + tid];
        const float upd  = fmaf(ci, 0.9f, mean * 0.1f);

        const float nrm2 = block_reduce_256(upd * upd, s_red, tid);
        const float v    = upd * rsqrtf(nrm2);

        const float d  = v - cskt[c * D_DIM + tid];
        const float sq = block_reduce_256(d * d, s_red, tid);

        if (tid == 0) {
            atomicAdd(&g_loss_sum, sq);
            atomicAdd(&g_n_present, 1);
        }
    }

    // Completion protocol: last block finalizes the scalar and resets scratch.
    if (tid == 0) {
        __threadfence();
        const int t = atomicAdd(&g_done, 1);
        if (t == (int)gridDim.x - 1) {
            const float ls = atomicAdd(&g_loss_sum, 0.0f);   // coherent read
            int np = atomicAdd(&g_n_present, 0);
            if (np < 1) np = 1;
            out[0] = ls / (float)np;
            g_loss_sum  = 0.0f;
            g_n_present = 0;
            g_done      = 0;
        }
    }
}

// ---------------------------------------------------------------------------
extern "C" void kernel_launch(void* const* d_in, const int* in_sizes, int n_in,
                              void* d_out, int out_size) {
    const float* x    = (const float*)d_in[0];
    const void*  lraw = d_in[1];
    const float* cimg = (const float*)d_in[2];
    const float* cskt = (const float*)d_in[3];
    float* out = (float*)d_out;

    const int B = in_sizes[1];           // 524288
    const int C = in_sizes[2] / D_DIM;   // 1000

    const int nb = (B + BIN_CHUNK - 1) / BIN_CHUNK;   // 256
    bin_kernel<<<nb, 1024>>>(lraw, B, C);
    class_kernel<<<C, 256>>>(x, cimg, cskt, out);
}

// round 15
// speedup vs baseline: 1.0818x; 1.0047x over previous
#include <cuda_runtime.h>
#include <cuda_bf16.h>

// B=524288, D=256, C=1000 (D hardcoded for thread-per-element layout).
// FINAL: exact R5 configuration — best measured (96.4us). Class kernel is at
// the order-invariant chip gather ceiling (~6.1 TB/s on 512MB mandatory
// traffic, verified across 7 runs / 6 falsified alternatives).
#define D_DIM 256
#define C_MAX 1024
#define BUCKET_CAP 2048     // expected ~524/class, Poisson max ~650
#define CNT_PAD 32          // one counter per 128B line -> distinct LTS slices
#define BIN_CHUNK 4096      // labels per bin block (128 blocks: optimum)

// Scratch: __device__ globals (zero-initialized at load; self-cleaned per run).
__device__ int   g_counts[C_MAX * CNT_PAD];   // padded counters (128 KB)
__device__ int   g_bucket[C_MAX * BUCKET_CAP];
__device__ float g_loss_sum;
__device__ int   g_n_present;
__device__ int   g_done;

// ---------------------------------------------------------------------------
// Kernel 1: two-level binning.
//   Phase A: decode labels once into smem + smem histogram.
//   Phase B: one padded global atomic per (block,class) reserves a bucket
//            range (128K atomics on 1000 distinct cache lines).
//   Phase C: write row indices at reserved offsets (semi-contiguous stores).
// Label dtype (int64 vs int32 storage) detected per-block by range-checking
// the first 1024 words interpreted as int64 — deterministic, L2-hot.
// ---------------------------------------------------------------------------
__global__ void __launch_bounds__(1024) bin_kernel(const void* __restrict__ lraw,
                                                   int B, int C) {
    __shared__ unsigned short s_lab[BIN_CHUNK];   // 8 KB
    __shared__ int s_hist[C_MAX];                 // 4 KB (hist, then cursor)
    __shared__ int s_base[C_MAX];                 // 4 KB
    __shared__ int s_bad;

    const int tid = threadIdx.x;
    if (tid == 0) s_bad = 0;
    for (int i = tid; i < C_MAX; i += 1024) s_hist[i] = 0;
    __syncthreads();

    const long long* __restrict__ l64 = (const long long*)lraw;
    const int* __restrict__       l32 = (const int*)lraw;

    {
        const int n = (B < 1024) ? B : 1024;
        int bad = 0;
        for (int i = tid; i < n; i += 1024) {
            const long long v = l64[i];
            if (v < 0 || v >= (long long)C) bad = 1;
        }
        if (bad) atomicOr(&s_bad, 1);
    }
    __syncthreads();
    const bool is64 = (s_bad == 0);

    const int start = blockIdx.x * BIN_CHUNK;
    const int end   = (start + BIN_CHUNK < B) ? (start + BIN_CHUNK) : B;
    const int cnt   = (end > start) ? (end - start) : 0;

    // Phase A: decode + local histogram
    for (int i = tid; i < cnt; i += 1024) {
        const int c = is64 ? (int)l64[start + i] : l32[start + i];
        s_lab[i] = (unsigned short)c;
        atomicAdd(&s_hist[c], 1);
    }
    __syncthreads();

    // Phase B: reserve global ranges; reset hist for reuse as cursor
    for (int c = tid; c < C; c += 1024) {
        const int h = s_hist[c];
        s_base[c] = h ? atomicAdd(&g_counts[c * CNT_PAD], h) : 0;
        s_hist[c] = 0;
    }
    __syncthreads();

    // Phase C: scatter row indices into reserved (contiguous) slots
    for (int i = tid; i < cnt; i += 1024) {
        const int c   = s_lab[i];
        const int pos = s_base[c] + atomicAdd(&s_hist[c], 1);
        if (pos < BUCKET_CAP) g_bucket[c * BUCKET_CAP + pos] = start + i;
    }
}

// ---------------------------------------------------------------------------
// Block reduce over 256 threads (8 warps)
// ---------------------------------------------------------------------------
__device__ __forceinline__ float block_reduce_256(float v, float* s_red, int tid) {
    #pragma unroll
    for (int o = 16; o > 0; o >>= 1) v += __shfl_down_sync(0xffffffffu, v, o);
    if ((tid & 31) == 0) s_red[tid >> 5] = v;
    __syncthreads();
    if (tid < 32) {
        v = (tid < 8) ? s_red[tid] : 0.0f;
        #pragma unroll
        for (int o = 4; o > 0; o >>= 1) v += __shfl_down_sync(0xffffffffu, v, o);
        if (tid == 0) s_red[0] = v;
    }
    __syncthreads();
    const float r = s_red[0];
    __syncthreads();
    return r;
}

// ---------------------------------------------------------------------------
// Kernel 2: one block per class. float4 gather (4 independent LDG.128 per
// thread in flight; 32 regs -> exactly 8 blocks/SM), mean, momentum update,
// L2-normalize, squared distance, masked-mean loss. Last finishing block
// writes the scalar output and resets all scratch (graph-replay safe).
// ---------------------------------------------------------------------------
__global__ void __launch_bounds__(256) class_kernel(
    const float* __restrict__ x,
    const float* __restrict__ cimg,
    const float* __restrict__ cskt,
    float* __restrict__ out)
{
    const int c   = blockIdx.x;
    const int tid = threadIdx.x;
    const int q   = tid >> 6;        // row slot 0..3
    const int ds  = tid & 63;        // float4 index within a 256-float row

    __shared__ __align__(16) float s_part[4 * 256];
    __shared__ __align__(16) int   s_rows[512];
    __shared__ float s_red[32];
    __shared__ int   s_count;

    if (tid == 0) {
        s_count = g_counts[c * CNT_PAD];
        g_counts[c * CNT_PAD] = 0;   // self-clean for next graph replay
    }
    __syncthreads();
    const int count = s_count;

    if (count > 0) {
        const int m = (count < BUCKET_CAP) ? count : BUCKET_CAP;
        const int* __restrict__ bucket = &g_bucket[c * BUCKET_CAP];

        float4 acc = make_float4(0.f, 0.f, 0.f, 0.f);

        for (int base = 0; base < m; base += 512) {
            const int seg = (m - base < 512) ? (m - base) : 512;
            __syncthreads();
            for (int t = tid; t < seg; t += 256) s_rows[t] = bucket[base + t];
            __syncthreads();

            int j = 0;
            for (; j + 16 <= seg; j += 16) {
                const int r0 = s_rows[j      + q];
                const int r1 = s_rows[j + 4  + q];
                const int r2 = s_rows[j + 8  + q];
                const int r3 = s_rows[j + 12 + q];
                const float4 v0 = __ldg((const float4*)(x + (size_t)r0 * D_DIM) + ds);
                const float4 v1 = __ldg((const float4*)(x + (size_t)r1 * D_DIM) + ds);
                const float4 v2 = __ldg((const float4*)(x + (size_t)r2 * D_DIM) + ds);
                const float4 v3 = __ldg((const float4*)(x + (size_t)r3 * D_DIM) + ds);
                acc.x += v0.x + v1.x + v2.x + v3.x;
                acc.y += v0.y + v1.y + v2.y + v3.y;
                acc.z += v0.z + v1.z + v2.z + v3.z;
                acc.w += v0.w + v1.w + v2.w + v3.w;
            }
            for (; j < seg; j += 4) {
                const int idx = j + q;
                if (idx < seg) {
                    const int r = s_rows[idx];
                    const float4 v = __ldg((const float4*)(x + (size_t)r * D_DIM) + ds);
                    acc.x += v.x; acc.y += v.y; acc.z += v.z; acc.w += v.w;
                }
            }
        }

        // Combine the 4 row-slot partial sums across q via smem.
        __syncthreads();
        *((float4*)(s_part + q * 256) + ds) = acc;
        __syncthreads();
        const float sum = s_part[0 * 256 + tid] + s_part[1 * 256 + tid] +
                          s_part[2 * 256 + tid] + s_part[3 * 256 + tid];

        const float mean = sum / (float)count;
        const float ci   = cimg[c * D_DIM + tid];
        const float upd  = fmaf(ci, 0.9f, mean * 0.1f);

        const float nrm2 = block_reduce_256(upd * upd, s_red, tid);
        const float v    = upd * rsqrtf(nrm2);

        const float d  = v - cskt[c * D_DIM + tid];
        const float sq = block_reduce_256(d * d, s_red, tid);

        if (tid == 0) {
            atomicAdd(&g_loss_sum, sq);
            atomicAdd(&g_n_present, 1);
        }
    }

    // Completion protocol: last block finalizes the scalar and resets scratch.
    if (tid == 0) {
        __threadfence();
        const int t = atomicAdd(&g_done, 1);
        if (t == (int)gridDim.x - 1) {
            const float ls = atomicAdd(&g_loss_sum, 0.0f);   // coherent read
            int np = atomicAdd(&g_n_present, 0);
            if (np < 1) np = 1;
            out[0] = ls / (float)np;
            g_loss_sum  = 0.0f;
            g_n_present = 0;
            g_done      = 0;
        }
    }
}

// ---------------------------------------------------------------------------
extern "C" void kernel_launch(void* const* d_in, const int* in_sizes, int n_in,
                              void* d_out, int out_size) {
    const float* x    = (const float*)d_in[0];
    const void*  lraw = d_in[1];
    const float* cimg = (const float*)d_in[2];
    const float* cskt = (const float*)d_in[3];
    float* out = (float*)d_out;

    const int B = in_sizes[1];           // 524288
    const int C = in_sizes[2] / D_DIM;   // 1000

    const int nb = (B + BIN_CHUNK - 1) / BIN_CHUNK;   // 128
    bin_kernel<<<nb, 1024>>>(lraw, B, C);
    class_kernel<<<C, 256>>>(x, cimg, cskt, out);
}

// round 16
// speedup vs baseline: 1.0821x; 1.0003x over previous
#include <cuda_runtime.h>
#include <cuda_bf16.h>

// B=524288, D=256, C=1000 (D hardcoded for thread-per-element layout).
// FINAL (converged, best measured 96.29us):
//   - two-level histogram binning (128 blocks), ~4.5us
//   - per-class float4 gather at the measured chip ceiling (~6.1 TB/s on
//     512MB mandatory traffic; order/MLP/occupancy/scheduling-invariant,
//     verified across 8 runs and 6 falsified alternatives R6-R14)
#define D_DIM 256
#define C_MAX 1024
#define BUCKET_CAP 2048     // expected ~524/class, Poisson max ~650
#define CNT_PAD 32          // one counter per 128B line -> distinct LTS slices
#define BIN_CHUNK 4096      // labels per bin block (128 blocks: optimum)

// Scratch: __device__ globals (zero-initialized at load; self-cleaned per run).
__device__ int   g_counts[C_MAX * CNT_PAD];   // padded counters (128 KB)
__device__ int   g_bucket[C_MAX * BUCKET_CAP];
__device__ float g_loss_sum;
__device__ int   g_n_present;
__device__ int   g_done;

// ---------------------------------------------------------------------------
// Kernel 1: two-level binning.
//   Phase A: decode labels once into smem + smem histogram.
//   Phase B: one padded global atomic per (block,class) reserves a bucket
//            range (128K atomics on 1000 distinct cache lines).
//   Phase C: write row indices at reserved offsets (semi-contiguous stores).
// Label dtype (int64 vs int32 storage) detected per-block by range-checking
// the first 1024 words interpreted as int64 — deterministic, L2-hot.
// ---------------------------------------------------------------------------
__global__ void __launch_bounds__(1024) bin_kernel(const void* __restrict__ lraw,
                                                   int B, int C) {
    __shared__ unsigned short s_lab[BIN_CHUNK];   // 8 KB
    __shared__ int s_hist[C_MAX];                 // 4 KB (hist, then cursor)
    __shared__ int s_base[C_MAX];                 // 4 KB
    __shared__ int s_bad;

    const int tid = threadIdx.x;
    if (tid == 0) s_bad = 0;
    for (int i = tid; i < C_MAX; i += 1024) s_hist[i] = 0;
    __syncthreads();

    const long long* __restrict__ l64 = (const long long*)lraw;
    const int* __restrict__       l32 = (const int*)lraw;

    {
        const int n = (B < 1024) ? B : 1024;
        int bad = 0;
        for (int i = tid; i < n; i += 1024) {
            const long long v = l64[i];
            if (v < 0 || v >= (long long)C) bad = 1;
        }
        if (bad) atomicOr(&s_bad, 1);
    }
    __syncthreads();
    const bool is64 = (s_bad == 0);

    const int start = blockIdx.x * BIN_CHUNK;
    const int end   = (start + BIN_CHUNK < B) ? (start + BIN_CHUNK) : B;
    const int cnt   = (end > start) ? (end - start) : 0;

    // Phase A: decode + local histogram
    for (int i = tid; i < cnt; i += 1024) {
        const int c = is64 ? (int)l64[start + i] : l32[start + i];
        s_lab[i] = (unsigned short)c;
        atomicAdd(&s_hist[c], 1);
    }
    __syncthreads();

    // Phase B: reserve global ranges; reset hist for reuse as cursor
    for (int c = tid; c < C; c += 1024) {
        const int h = s_hist[c];
        s_base[c] = h ? atomicAdd(&g_counts[c * CNT_PAD], h) : 0;
        s_hist[c] = 0;
    }
    __syncthreads();

    // Phase C: scatter row indices into reserved (contiguous) slots
    for (int i = tid; i < cnt; i += 1024) {
        const int c   = s_lab[i];
        const int pos = s_base[c] + atomicAdd(&s_hist[c], 1);
        if (pos < BUCKET_CAP) g_bucket[c * BUCKET_CAP + pos] = start + i;
    }
}

// ---------------------------------------------------------------------------
// Block reduce over 256 threads (8 warps)
// ---------------------------------------------------------------------------
__device__ __forceinline__ float block_reduce_256(float v, float* s_red, int tid) {
    #pragma unroll
    for (int o = 16; o > 0; o >>= 1) v += __shfl_down_sync(0xffffffffu, v, o);
    if ((tid & 31) == 0) s_red[tid >> 5] = v;
    __syncthreads();
    if (tid < 32) {
        v = (tid < 8) ? s_red[tid] : 0.0f;
        #pragma unroll
        for (int o = 4; o > 0; o >>= 1) v += __shfl_down_sync(0xffffffffu, v, o);
        if (tid == 0) s_red[0] = v;
    }
    __syncthreads();
    const float r = s_red[0];
    __syncthreads();
    return r;
}

// ---------------------------------------------------------------------------
// Kernel 2: one block per class. float4 gather (4 independent LDG.128 per
// thread in flight; exactly 32 regs -> 8 blocks/SM = full RF), mean, momentum
// update, L2-normalize, squared distance, masked-mean loss. Last finishing
// block writes the scalar output and resets all scratch (graph-replay safe).
// ---------------------------------------------------------------------------
__global__ void __launch_bounds__(256) class_kernel(
    const float* __restrict__ x,
    const float* __restrict__ cimg,
    const float* __restrict__ cskt,
    float* __restrict__ out)
{
    const int c   = blockIdx.x;
    const int tid = threadIdx.x;
    const int q   = tid >> 6;        // row slot 0..3
    const int ds  = tid & 63;        // float4 index within a 256-float row

    __shared__ __align__(16) float s_part[4 * 256];
    __shared__ __align__(16) int   s_rows[512];
    __shared__ float s_red[32];
    __shared__ int   s_count;

    if (tid == 0) {
        s_count = g_counts[c * CNT_PAD];
        g_counts[c * CNT_PAD] = 0;   // self-clean for next graph replay
    }
    __syncthreads();
    const int count = s_count;

    if (count > 0) {
        const int m = (count < BUCKET_CAP) ? count : BUCKET_CAP;
        const int* __restrict__ bucket = &g_bucket[c * BUCKET_CAP];

        float4 acc = make_float4(0.f, 0.f, 0.f, 0.f);

        for (int base = 0; base < m; base += 512) {
            const int seg = (m - base < 512) ? (m - base) : 512;
            __syncthreads();
            for (int t = tid; t < seg; t += 256) s_rows[t] = bucket[base + t];
            __syncthreads();

            int j = 0;
            for (; j + 16 <= seg; j += 16) {
                const int r0 = s_rows[j      + q];
                const int r1 = s_rows[j + 4  + q];
                const int r2 = s_rows[j + 8  + q];
                const int r3 = s_rows[j + 12 + q];
                const float4 v0 = __ldg((const float4*)(x + (size_t)r0 * D_DIM) + ds);
                const float4 v1 = __ldg((const float4*)(x + (size_t)r1 * D_DIM) + ds);
                const float4 v2 = __ldg((const float4*)(x + (size_t)r2 * D_DIM) + ds);
                const float4 v3 = __ldg((const float4*)(x + (size_t)r3 * D_DIM) + ds);
                acc.x += v0.x + v1.x + v2.x + v3.x;
                acc.y += v0.y + v1.y + v2.y + v3.y;
                acc.z += v0.z + v1.z + v2.z + v3.z;
                acc.w += v0.w + v1.w + v2.w + v3.w;
            }
            for (; j < seg; j += 4) {
                const int idx = j + q;
                if (idx < seg) {
                    const int r = s_rows[idx];
                    const float4 v = __ldg((const float4*)(x + (size_t)r * D_DIM) + ds);
                    acc.x += v.x; acc.y += v.y; acc.z += v.z; acc.w += v.w;
                }
            }
        }

        // Combine the 4 row-slot partial sums across q via smem.
        __syncthreads();
        *((float4*)(s_part + q * 256) + ds) = acc;
        __syncthreads();
        const float sum = s_part[0 * 256 + tid] + s_part[1 * 256 + tid] +
                          s_part[2 * 256 + tid] + s_part[3 * 256 + tid];

        const float mean = sum / (float)count;
        const float ci   = cimg[c * D_DIM + tid];
        const float upd  = fmaf(ci, 0.9f, mean * 0.1f);

        const float nrm2 = block_reduce_256(upd * upd, s_red, tid);
        const float v    = upd * rsqrtf(nrm2);

        const float d  = v - cskt[c * D_DIM + tid];
        const float sq = block_reduce_256(d * d, s_red, tid);

        if (tid == 0) {
            atomicAdd(&g_loss_sum, sq);
            atomicAdd(&g_n_present, 1);
        }
    }

    // Completion protocol: last block finalizes the scalar and resets scratch.
    if (tid == 0) {
        __threadfence();
        const int t = atomicAdd(&g_done, 1);
        if (t == (int)gridDim.x - 1) {
            const float ls = atomicAdd(&g_loss_sum, 0.0f);   // coherent read
            int np = atomicAdd(&g_n_present, 0);
            if (np < 1) np = 1;
            out[0] = ls / (float)np;
            g_loss_sum  = 0.0f;
            g_n_present = 0;
            g_done      = 0;
        }
    }
}

// ---------------------------------------------------------------------------
extern "C" void kernel_launch(void* const* d_in, const int* in_sizes, int n_in,
                              void* d_out, int out_size) {
    const float* x    = (const float*)d_in[0];
    const void*  lraw = d_in[1];
    const float* cimg = (const float*)d_in[2];
    const float* cskt = (const float*)d_in[3];
    float* out = (float*)d_out;

    const int B = in_sizes[1];           // 524288
    const int C = in_sizes[2] / D_DIM;   // 1000

    const int nb = (B + BIN_CHUNK - 1) / BIN_CHUNK;   // 128
    bin_kernel<<<nb, 1024>>>(lraw, B, C);
    class_kernel<<<C, 256>>>(x, cimg, cskt, out);
}